// round 7
// baseline (speedup 1.0000x reference)
#include <cuda_runtime.h>
#include <cuda_bf16.h>
#include <math.h>

// ---------------- problem constants ----------------
#define N_ENT 50000
#define DIM   128
#define E_NUM 200000
#define S_NUM 20000
#define NREL  200
#define NBASES 4
#define KTOT  640          // 128 (x/root) + 4*128 (Z/basis)
#define ZCOLS (NBASES * DIM)   // 512

// ---------------- device scratch (no runtime alloc allowed) ----------------
__device__ float g_X[2][N_ENT * DIM];            // ping-pong node features (fp32)
__device__ __nv_bfloat16 g_Z[(size_t)N_ENT * ZCOLS];  // input-space aggregates (bf16)
__device__ float g_inv[N_ENT];
__device__ int   g_icnt[N_ENT];
__device__ int   g_cur[N_ENT];
__device__ int   g_off[N_ENT + 1];
__device__ int   g_esrc[E_NUM];
__device__ int   g_est[E_NUM];
__device__ float g_esn[E_NUM];
__device__ float g_W2[KTOT * DIM];               // stacked [root ; basis] weights
__device__ float g_T[NREL * DIM];                // DAD @ rel_ctx
__device__ float g_R[NREL * DIM];                // relu(T @ Wgcn)

// ---------------- helpers ----------------
__device__ __forceinline__ unsigned f2tf32(float x) {
    unsigned u;
    asm("cvt.rna.tf32.f32 %0, %1;" : "=r"(u) : "f"(x));
    return u;
}

// ---------------- CSR build ----------------
__global__ void k_zero_cnt() {
    int i = blockIdx.x * blockDim.x + threadIdx.x;
    if (i < N_ENT) { g_icnt[i] = 0; g_cur[i] = 0; }
}

__global__ void k_count(const int* __restrict__ ei) {
    int e = blockIdx.x * blockDim.x + threadIdx.x;
    if (e < E_NUM) atomicAdd(&g_icnt[ei[E_NUM + e]], 1);
}

__global__ void k_inv() {
    int i = blockIdx.x * blockDim.x + threadIdx.x;
    if (i < N_ENT) g_inv[i] = 1.0f / fmaxf((float)g_icnt[i], 1.0f);
}

// single-block exclusive scan of g_icnt -> g_off
__global__ void k_scan() {
    __shared__ int part[1024];
    int tid = threadIdx.x;
    const int CH = (N_ENT + 1023) / 1024;   // 49
    int base = tid * CH;
    int s = 0;
    for (int i = 0; i < CH; i++) {
        int idx = base + i;
        if (idx < N_ENT) s += g_icnt[idx];
    }
    part[tid] = s;
    __syncthreads();
    for (int off = 1; off < 1024; off <<= 1) {
        int v = (tid >= off) ? part[tid - off] : 0;
        __syncthreads();
        part[tid] += v;
        __syncthreads();
    }
    int run = (tid == 0) ? 0 : part[tid - 1];
    for (int i = 0; i < CH; i++) {
        int idx = base + i;
        if (idx < N_ENT) { g_off[idx] = run; run += g_icnt[idx]; }
    }
    if (tid == 1023) g_off[N_ENT] = run;
}

__global__ void k_scatter(const int* __restrict__ ei,
                          const int* __restrict__ etype,
                          const float* __restrict__ enorm) {
    int e = blockIdx.x * blockDim.x + threadIdx.x;
    if (e >= E_NUM) return;
    int dst = ei[E_NUM + e];
    int slot = g_off[dst] + atomicAdd(&g_cur[dst], 1);
    g_esrc[slot] = ei[e];
    g_est[slot]  = etype[e];
    g_esn[slot]  = enorm[e];
}

// ---------------- initial feature gather ----------------
__global__ void k_gather(const int* __restrict__ entity, const float* __restrict__ ectx) {
    int idx = blockIdx.x * blockDim.x + threadIdx.x;   // float4 index
    if (idx >= N_ENT * (DIM / 4)) return;
    int n = idx >> 5, c = idx & 31;
    ((float4*)g_X[0])[idx] = ((const float4*)ectx)[(size_t)entity[n] * 32 + c];
}

// ---------------- pack stacked weight: rows 0..127 root, 128.. basis ----------------
__global__ void k_pack(const float* __restrict__ basis, const float* __restrict__ root) {
    int idx = blockIdx.x * blockDim.x + threadIdx.x;
    if (idx >= KTOT * DIM) return;
    int r = idx >> 7, o = idx & 127;
    float v;
    if (r < DIM) v = root[(size_t)r * DIM + o];
    else         v = basis[(size_t)(r - DIM) * DIM + o];   // (r-128) = b*128+i, contiguous
    g_W2[idx] = v;
}

// ---------------- input-space aggregation: Z[dst] = inv * sum_e c_b * x[src] ----------------
// one warp per dst node; lane owns dims [lane*4, lane*4+3]
__global__ void __launch_bounds__(256) k_aggZ(int xbuf, const float* __restrict__ att) {
    int n = blockIdx.x * 8 + (threadIdx.x >> 5);
    if (n >= N_ENT) return;
    int lane = threadIdx.x & 31;
    const float* X = g_X[xbuf];

    float a0x=0,a0y=0,a0z=0,a0w=0, a1x=0,a1y=0,a1z=0,a1w=0;
    float a2x=0,a2y=0,a2z=0,a2w=0, a3x=0,a3y=0,a3z=0,a3w=0;

    int beg = g_off[n], end = g_off[n + 1];
    for (int i = beg; i < end; i++) {
        int src  = __ldg(g_esrc + i);
        int t    = __ldg(g_est + i);
        float nr = __ldg(g_esn + i);
        float4 c = __ldg((const float4*)att + t);
        float c0 = nr * c.x, c1 = nr * c.y, c2 = nr * c.z, c3 = nr * c.w;
        float4 x = *(const float4*)(X + (size_t)src * DIM + lane * 4);
        a0x += c0*x.x; a0y += c0*x.y; a0z += c0*x.z; a0w += c0*x.w;
        a1x += c1*x.x; a1y += c1*x.y; a1z += c1*x.z; a1w += c1*x.w;
        a2x += c2*x.x; a2y += c2*x.y; a2z += c2*x.z; a2w += c2*x.w;
        a3x += c3*x.x; a3y += c3*x.y; a3z += c3*x.z; a3w += c3*x.w;
    }
    float inv = g_inv[n];
    __nv_bfloat16* Zr = g_Z + (size_t)n * ZCOLS;
    *(__nv_bfloat162*)(Zr + 0*DIM + lane*4)     = __floats2bfloat162_rn(a0x*inv, a0y*inv);
    *(__nv_bfloat162*)(Zr + 0*DIM + lane*4 + 2) = __floats2bfloat162_rn(a0z*inv, a0w*inv);
    *(__nv_bfloat162*)(Zr + 1*DIM + lane*4)     = __floats2bfloat162_rn(a1x*inv, a1y*inv);
    *(__nv_bfloat162*)(Zr + 1*DIM + lane*4 + 2) = __floats2bfloat162_rn(a1z*inv, a1w*inv);
    *(__nv_bfloat162*)(Zr + 2*DIM + lane*4)     = __floats2bfloat162_rn(a2x*inv, a2y*inv);
    *(__nv_bfloat162*)(Zr + 2*DIM + lane*4 + 2) = __floats2bfloat162_rn(a2z*inv, a2w*inv);
    *(__nv_bfloat162*)(Zr + 3*DIM + lane*4)     = __floats2bfloat162_rn(a3x*inv, a3y*inv);
    *(__nv_bfloat162*)(Zr + 3*DIM + lane*4 + 2) = __floats2bfloat162_rn(a3z*inv, a3w*inv);
}

// ---------------- fused GEMM: Xn = relu([X|Z] @ W2 + bias) ----------------
// CTA tile 128x128, 8 warps (4 m x 2 n), mma.m16n8k8.tf32, K = 640 (20 chunks of 32).
#define SMSTRIDE 36

__global__ void __launch_bounds__(256, 2) k_gemm(int xbuf, int obuf,
                                                 const float* __restrict__ bias) {
    __shared__ unsigned As[128 * SMSTRIDE];   // [m][k] tf32
    __shared__ unsigned Bt[128 * SMSTRIDE];   // [n][k] tf32 (W2 transposed)

    const float* X = g_X[xbuf];
    int tid = threadIdx.x;
    int lane = tid & 31, wid = tid >> 5;
    int warp_m = wid & 3, warp_n = wid >> 1 & 1;   // wid: m = wid&3, n = wid>>2
    warp_n = wid >> 2;
    int g = lane >> 2, tig = lane & 3;
    int m0 = blockIdx.x * 128;

    float d[2][8][4];
    #pragma unroll
    for (int mi = 0; mi < 2; mi++)
        #pragma unroll
        for (int ni = 0; ni < 8; ni++)
            #pragma unroll
            for (int q = 0; q < 4; q++) d[mi][ni][q] = 0.0f;

    #pragma unroll 1
    for (int c = 0; c < 20; c++) {
        int k0 = c * 32;
        // ---- A chunk: 128 rows x 32 k ----
        if (c < 4) {
            // from X (fp32)
            #pragma unroll
            for (int t = 0; t < 4; t++) {
                int idx = tid + t * 256;
                int row = idx >> 3, c4 = idx & 7;
                float4 v = make_float4(0.f, 0.f, 0.f, 0.f);
                if (m0 + row < N_ENT)
                    v = *(const float4*)(X + (size_t)(m0 + row) * DIM + k0 + c4 * 4);
                unsigned* p = As + row * SMSTRIDE + c4 * 4;
                p[0] = f2tf32(v.x); p[1] = f2tf32(v.y);
                p[2] = f2tf32(v.z); p[3] = f2tf32(v.w);
            }
        } else {
            // from Z (bf16): 32 bf16 per row = 4 uint4
            int zc0 = k0 - DIM;
            #pragma unroll
            for (int t = 0; t < 2; t++) {
                int idx = tid + t * 256;
                int row = idx >> 2, q = idx & 3;
                uint4 v = make_uint4(0u, 0u, 0u, 0u);
                if (m0 + row < N_ENT)
                    v = *(const uint4*)(g_Z + (size_t)(m0 + row) * ZCOLS + zc0 + q * 8);
                unsigned* p = As + row * SMSTRIDE + q * 8;
                const __nv_bfloat162* h = (const __nv_bfloat162*)&v;
                #pragma unroll
                for (int j = 0; j < 4; j++) {
                    float2 f = __bfloat1622float2(h[j]);
                    p[j * 2]     = f2tf32(f.x);
                    p[j * 2 + 1] = f2tf32(f.y);
                }
            }
        }
        // ---- B chunk: 32 k-rows x 128 n (transpose to [n][k]) ----
        #pragma unroll
        for (int t = 0; t < 4; t++) {
            int idx = tid + t * 256;
            int kr = idx & 31, c4 = idx >> 5;
            float4 v = *(const float4*)(g_W2 + (size_t)(k0 + kr) * DIM + c4 * 4);
            Bt[(c4 * 4 + 0) * SMSTRIDE + kr] = f2tf32(v.x);
            Bt[(c4 * 4 + 1) * SMSTRIDE + kr] = f2tf32(v.y);
            Bt[(c4 * 4 + 2) * SMSTRIDE + kr] = f2tf32(v.z);
            Bt[(c4 * 4 + 3) * SMSTRIDE + kr] = f2tf32(v.w);
        }
        __syncthreads();

        #pragma unroll
        for (int kk = 0; kk < 4; kk++) {
            unsigned a[2][4], b[8][2];
            #pragma unroll
            for (int mi = 0; mi < 2; mi++) {
                int br = warp_m * 32 + mi * 16;
                a[mi][0] = As[(br + g) * SMSTRIDE + kk * 8 + tig];
                a[mi][1] = As[(br + g + 8) * SMSTRIDE + kk * 8 + tig];
                a[mi][2] = As[(br + g) * SMSTRIDE + kk * 8 + tig + 4];
                a[mi][3] = As[(br + g + 8) * SMSTRIDE + kk * 8 + tig + 4];
            }
            #pragma unroll
            for (int ni = 0; ni < 8; ni++) {
                int bn = warp_n * 64 + ni * 8;
                b[ni][0] = Bt[(bn + g) * SMSTRIDE + kk * 8 + tig];
                b[ni][1] = Bt[(bn + g) * SMSTRIDE + kk * 8 + tig + 4];
            }
            #pragma unroll
            for (int mi = 0; mi < 2; mi++)
                #pragma unroll
                for (int ni = 0; ni < 8; ni++) {
                    asm volatile(
                        "mma.sync.aligned.m16n8k8.row.col.f32.tf32.tf32.f32 "
                        "{%0,%1,%2,%3}, {%4,%5,%6,%7}, {%8,%9}, {%0,%1,%2,%3};"
                        : "+f"(d[mi][ni][0]), "+f"(d[mi][ni][1]),
                          "+f"(d[mi][ni][2]), "+f"(d[mi][ni][3])
                        : "r"(a[mi][0]), "r"(a[mi][1]), "r"(a[mi][2]), "r"(a[mi][3]),
                          "r"(b[ni][0]), "r"(b[ni][1]));
                }
        }
        __syncthreads();
    }

    // epilogue: + bias, relu, store fp32 to X[obuf]
    float* Xo = g_X[obuf];
    #pragma unroll
    for (int mi = 0; mi < 2; mi++) {
        int r0 = m0 + warp_m * 32 + mi * 16 + g;
        #pragma unroll
        for (int ni = 0; ni < 8; ni++) {
            int col = warp_n * 64 + ni * 8 + tig * 2;
            float b0 = __ldg(bias + col), b1 = __ldg(bias + col + 1);
            if (r0 < N_ENT) {
                float2 o = make_float2(fmaxf(d[mi][ni][0] + b0, 0.f),
                                       fmaxf(d[mi][ni][1] + b1, 0.f));
                *(float2*)(Xo + (size_t)r0 * DIM + col) = o;
            }
            if (r0 + 8 < N_ENT) {
                float2 o = make_float2(fmaxf(d[mi][ni][2] + b0, 0.f),
                                       fmaxf(d[mi][ni][3] + b1, 0.f));
                *(float2*)(Xo + (size_t)(r0 + 8) * DIM + col) = o;
            }
        }
    }
}

// ---------------- relation path (tiny) ----------------
__global__ void k_relT(const float* __restrict__ DAD, const float* __restrict__ rctx) {
    int idx = blockIdx.x * blockDim.x + threadIdx.x;
    if (idx >= NREL * DIM) return;
    int r = idx >> 7, o = idx & 127;
    float s = 0.f;
    for (int k = 0; k < NREL; k++)
        s += DAD[r * NREL + k] * rctx[k * DIM + o];
    g_T[idx] = s;
}

__global__ void k_relR(const float* __restrict__ W) {
    int idx = blockIdx.x * blockDim.x + threadIdx.x;
    if (idx >= NREL * DIM) return;
    int r = idx >> 7, o = idx & 127;
    float s = 0.f;
    for (int k = 0; k < DIM; k++)
        s += g_T[r * DIM + k] * W[k * DIM + o];
    g_R[idx] = fmaxf(s, 0.f);
}

// ---------------- final gated gather ----------------
__global__ void k_out(const int* __restrict__ samples,
                      const float* __restrict__ ent_emb,
                      const float* __restrict__ rel_emb,
                      const float* __restrict__ gate_e,
                      const float* __restrict__ gate_r,
                      int x2buf, float* __restrict__ out) {
    int idx = blockIdx.x * blockDim.x + threadIdx.x;
    if (idx >= S_NUM * DIM) return;
    int s = idx >> 7, d = idx & 127;
    int h = samples[s * 3 + 0];
    int r = samples[s * 3 + 1];
    int t = samples[s * 3 + 2];
    float ge = 1.0f / (1.0f + expf(-gate_e[d]));
    float gr = 1.0f / (1.0f + expf(-gate_r[d]));
    const float* X2 = g_X[x2buf];
    out[idx] = ge * ent_emb[(size_t)h * DIM + d] + (1.0f - ge) * X2[(size_t)h * DIM + d];
    out[S_NUM * DIM + idx] = gr * rel_emb[(size_t)r * DIM + d] + (1.0f - gr) * g_R[(size_t)r * DIM + d];
    out[2 * S_NUM * DIM + idx] = ge * ent_emb[(size_t)t * DIM + d] + (1.0f - ge) * X2[(size_t)t * DIM + d];
}

// ---------------- launch ----------------
extern "C" void kernel_launch(void* const* d_in, const int* in_sizes, int n_in,
                              void* d_out, int out_size) {
    const int*   entity    = (const int*)d_in[0];
    const int*   edge_index= (const int*)d_in[1];
    const int*   edge_type = (const int*)d_in[2];
    const float* edge_norm = (const float*)d_in[3];
    const int*   samples   = (const int*)d_in[4];
    const float* DAD       = (const float*)d_in[5];
    const float* ent_emb   = (const float*)d_in[6];
    const float* rel_emb   = (const float*)d_in[7];
    const float* ectx      = (const float*)d_in[8];
    const float* rctx      = (const float*)d_in[9];
    const float* gcnW      = (const float*)d_in[10];
    const float* gate_e    = (const float*)d_in[11];
    const float* gate_r    = (const float*)d_in[12];
    const float* basis1    = (const float*)d_in[13];
    const float* att1      = (const float*)d_in[14];
    const float* root1     = (const float*)d_in[15];
    const float* bias1     = (const float*)d_in[16];
    const float* basis2    = (const float*)d_in[17];
    const float* att2      = (const float*)d_in[18];
    const float* root2     = (const float*)d_in[19];
    const float* bias2     = (const float*)d_in[20];
    float* out = (float*)d_out;

    const int THR = 256;
    int gemm_grid = (N_ENT + 127) / 128;

    // ---- CSR build (shared by both layers) ----
    k_zero_cnt<<<(N_ENT + THR - 1) / THR, THR>>>();
    k_count<<<(E_NUM + THR - 1) / THR, THR>>>(edge_index);
    k_inv<<<(N_ENT + THR - 1) / THR, THR>>>();
    k_scan<<<1, 1024>>>();
    k_scatter<<<(E_NUM + THR - 1) / THR, THR>>>(edge_index, edge_type, edge_norm);

    // initial features
    k_gather<<<(N_ENT * (DIM / 4) + THR - 1) / THR, THR>>>(entity, ectx);

    // ---- layer 1 ----
    k_pack<<<(KTOT * DIM + THR - 1) / THR, THR>>>(basis1, root1);
    k_aggZ<<<(N_ENT + 7) / 8, THR>>>(0, att1);
    k_gemm<<<gemm_grid, THR>>>(0, 1, bias1);

    // ---- layer 2 ----
    k_pack<<<(KTOT * DIM + THR - 1) / THR, THR>>>(basis2, root2);
    k_aggZ<<<(N_ENT + 7) / 8, THR>>>(1, att2);
    k_gemm<<<gemm_grid, THR>>>(1, 0, bias2);

    // ---- relation path ----
    k_relT<<<(NREL * DIM + THR - 1) / THR, THR>>>(DAD, rctx);
    k_relR<<<(NREL * DIM + THR - 1) / THR, THR>>>(gcnW);

    // ---- output ----
    k_out<<<(S_NUM * DIM + THR - 1) / THR, THR>>>(samples, ent_emb, rel_emb,
                                                  gate_e, gate_r, 0, out);
}

// round 8
// speedup vs baseline: 1.1615x; 1.1615x over previous
#include <cuda_runtime.h>
#include <cuda_bf16.h>
#include <math.h>

// ---------------- problem constants ----------------
#define N_ENT 50000
#define DIM   128
#define E_NUM 200000
#define S_NUM 20000
#define NREL  200
#define NBASES 4
#define KTOT  640              // 128 (x/root) + 4*128 (Z/basis)
#define ZCOLS (NBASES * DIM)   // 512
#define SCAN_BLK 256
#define SCAN_NBLK ((N_ENT + SCAN_BLK - 1) / SCAN_BLK)   // 196

// ---------------- device scratch (no runtime alloc allowed) ----------------
__device__ float g_X[2][N_ENT * DIM];                 // ping-pong node features (fp32)
__device__ __nv_bfloat16 g_Z[(size_t)N_ENT * ZCOLS];  // input-space aggregates (bf16)
__device__ float g_inv[N_ENT];
__device__ int   g_icnt[N_ENT];
__device__ int   g_cur[N_ENT];
__device__ int   g_off[N_ENT + 1];
__device__ int   g_pref[N_ENT];        // within-block exclusive prefix
__device__ int   g_btot[SCAN_NBLK];    // per-block totals
__device__ int   g_boff[SCAN_NBLK];    // scanned block offsets
__device__ int   g_esrc[E_NUM];
__device__ int   g_est[E_NUM];
__device__ float g_esn[E_NUM];
__device__ float g_T[NREL * DIM];      // DAD @ rel_ctx
__device__ float g_R[NREL * DIM];      // relu(T @ Wgcn)

// ---------------- helpers ----------------
__device__ __forceinline__ unsigned f2tf32(float x) {
    unsigned u;
    asm("cvt.rna.tf32.f32 %0, %1;" : "=r"(u) : "f"(x));
    return u;
}

// ---------------- CSR build ----------------
__global__ void k_zero_cnt() {
    int i = blockIdx.x * blockDim.x + threadIdx.x;
    if (i < N_ENT) { g_icnt[i] = 0; g_cur[i] = 0; }
}

__global__ void k_count(const int* __restrict__ ei) {
    int e = blockIdx.x * blockDim.x + threadIdx.x;
    if (e < E_NUM) atomicAdd(&g_icnt[ei[E_NUM + e]], 1);
}

// stage 1: per-block exclusive scan + block total
__global__ void k_bsum() {
    __shared__ int sh[SCAN_BLK];
    int t = threadIdx.x;
    int i = blockIdx.x * SCAN_BLK + t;
    int v = (i < N_ENT) ? g_icnt[i] : 0;
    // inclusive scan in smem
    sh[t] = v;
    __syncthreads();
    #pragma unroll
    for (int off = 1; off < SCAN_BLK; off <<= 1) {
        int u = (t >= off) ? sh[t - off] : 0;
        __syncthreads();
        sh[t] += u;
        __syncthreads();
    }
    if (i < N_ENT) g_pref[i] = sh[t] - v;      // exclusive
    if (t == SCAN_BLK - 1) g_btot[blockIdx.x] = sh[t];
}

// stage 2: scan of block totals (single small block)
__global__ void k_bscan() {
    __shared__ int sh[SCAN_NBLK];
    int t = threadIdx.x;
    int v = (t < SCAN_NBLK) ? g_btot[t] : 0;
    if (t < SCAN_NBLK) sh[t] = v;
    __syncthreads();
    for (int off = 1; off < SCAN_NBLK; off <<= 1) {
        int u = (t >= off && t < SCAN_NBLK) ? sh[t - off] : 0;
        __syncthreads();
        if (t < SCAN_NBLK) sh[t] += u;
        __syncthreads();
    }
    if (t < SCAN_NBLK) g_boff[t] = sh[t] - v;  // exclusive
    if (t == SCAN_NBLK - 1) g_off[N_ENT] = sh[t];
}

// stage 3: expand + inv
__global__ void k_expand() {
    int i = blockIdx.x * blockDim.x + threadIdx.x;
    if (i >= N_ENT) return;
    g_off[i] = g_pref[i] + g_boff[i / SCAN_BLK];
    g_inv[i] = 1.0f / fmaxf((float)g_icnt[i], 1.0f);
}

__global__ void k_scatter(const int* __restrict__ ei,
                          const int* __restrict__ etype,
                          const float* __restrict__ enorm) {
    int e = blockIdx.x * blockDim.x + threadIdx.x;
    if (e >= E_NUM) return;
    int dst = ei[E_NUM + e];
    int slot = g_off[dst] + atomicAdd(&g_cur[dst], 1);
    g_esrc[slot] = ei[e];
    g_est[slot]  = etype[e];
    g_esn[slot]  = enorm[e];
}

// ---------------- initial feature gather ----------------
__global__ void k_gather(const int* __restrict__ entity, const float* __restrict__ ectx) {
    int idx = blockIdx.x * blockDim.x + threadIdx.x;   // float4 index
    if (idx >= N_ENT * (DIM / 4)) return;
    int n = idx >> 5, c = idx & 31;
    ((float4*)g_X[0])[idx] = ((const float4*)ectx)[(size_t)entity[n] * 32 + c];
}

// ---------------- input-space aggregation: Z[dst] = inv * sum_e c_b * x[src] ----------------
// one warp per dst node; lane owns dims [lane*4, lane*4+3]; 2-edge unroll for MLP.
__global__ void __launch_bounds__(256) k_aggZ(int xbuf, const float* __restrict__ att) {
    int n = blockIdx.x * 8 + (threadIdx.x >> 5);
    if (n >= N_ENT) return;
    int lane = threadIdx.x & 31;
    const float* X = g_X[xbuf];

    float a0x=0,a0y=0,a0z=0,a0w=0, a1x=0,a1y=0,a1z=0,a1w=0;
    float a2x=0,a2y=0,a2z=0,a2w=0, a3x=0,a3y=0,a3z=0,a3w=0;

    int beg = g_off[n], end = g_off[n + 1];
    int i = beg;
    for (; i + 1 < end; i += 2) {
        int srcA  = __ldg(g_esrc + i),     srcB  = __ldg(g_esrc + i + 1);
        int tA    = __ldg(g_est + i),      tB    = __ldg(g_est + i + 1);
        float nrA = __ldg(g_esn + i),      nrB   = __ldg(g_esn + i + 1);
        float4 cA = __ldg((const float4*)att + tA);
        float4 cB = __ldg((const float4*)att + tB);
        float4 xA = *(const float4*)(X + (size_t)srcA * DIM + lane * 4);
        float4 xB = *(const float4*)(X + (size_t)srcB * DIM + lane * 4);
        float c0 = nrA * cA.x, c1 = nrA * cA.y, c2 = nrA * cA.z, c3 = nrA * cA.w;
        a0x += c0*xA.x; a0y += c0*xA.y; a0z += c0*xA.z; a0w += c0*xA.w;
        a1x += c1*xA.x; a1y += c1*xA.y; a1z += c1*xA.z; a1w += c1*xA.w;
        a2x += c2*xA.x; a2y += c2*xA.y; a2z += c2*xA.z; a2w += c2*xA.w;
        a3x += c3*xA.x; a3y += c3*xA.y; a3z += c3*xA.z; a3w += c3*xA.w;
        c0 = nrB * cB.x; c1 = nrB * cB.y; c2 = nrB * cB.z; c3 = nrB * cB.w;
        a0x += c0*xB.x; a0y += c0*xB.y; a0z += c0*xB.z; a0w += c0*xB.w;
        a1x += c1*xB.x; a1y += c1*xB.y; a1z += c1*xB.z; a1w += c1*xB.w;
        a2x += c2*xB.x; a2y += c2*xB.y; a2z += c2*xB.z; a2w += c2*xB.w;
        a3x += c3*xB.x; a3y += c3*xB.y; a3z += c3*xB.z; a3w += c3*xB.w;
    }
    if (i < end) {
        int src  = __ldg(g_esrc + i);
        int t    = __ldg(g_est + i);
        float nr = __ldg(g_esn + i);
        float4 c = __ldg((const float4*)att + t);
        float4 x = *(const float4*)(X + (size_t)src * DIM + lane * 4);
        float c0 = nr * c.x, c1 = nr * c.y, c2 = nr * c.z, c3 = nr * c.w;
        a0x += c0*x.x; a0y += c0*x.y; a0z += c0*x.z; a0w += c0*x.w;
        a1x += c1*x.x; a1y += c1*x.y; a1z += c1*x.z; a1w += c1*x.w;
        a2x += c2*x.x; a2y += c2*x.y; a2z += c2*x.z; a2w += c2*x.w;
        a3x += c3*x.x; a3y += c3*x.y; a3z += c3*x.z; a3w += c3*x.w;
    }
    float inv = g_inv[n];
    __nv_bfloat16* Zr = g_Z + (size_t)n * ZCOLS;
    *(__nv_bfloat162*)(Zr + 0*DIM + lane*4)     = __floats2bfloat162_rn(a0x*inv, a0y*inv);
    *(__nv_bfloat162*)(Zr + 0*DIM + lane*4 + 2) = __floats2bfloat162_rn(a0z*inv, a0w*inv);
    *(__nv_bfloat162*)(Zr + 1*DIM + lane*4)     = __floats2bfloat162_rn(a1x*inv, a1y*inv);
    *(__nv_bfloat162*)(Zr + 1*DIM + lane*4 + 2) = __floats2bfloat162_rn(a1z*inv, a1w*inv);
    *(__nv_bfloat162*)(Zr + 2*DIM + lane*4)     = __floats2bfloat162_rn(a2x*inv, a2y*inv);
    *(__nv_bfloat162*)(Zr + 2*DIM + lane*4 + 2) = __floats2bfloat162_rn(a2z*inv, a2w*inv);
    *(__nv_bfloat162*)(Zr + 3*DIM + lane*4)     = __floats2bfloat162_rn(a3x*inv, a3y*inv);
    *(__nv_bfloat162*)(Zr + 3*DIM + lane*4 + 2) = __floats2bfloat162_rn(a3z*inv, a3w*inv);
}

// ---------------- fused GEMM: Xn = relu([X|Z] @ [root;basis] + bias) ----------------
// CTA tile 128x128, 8 warps (4 m x 2 n), mma.m16n8k8.tf32, K = 640 (20 chunks of 32).
// B tiles are read DIRECTLY from root (chunks 0..3) / basis (chunks 4..19).
#define SMSTRIDE 36

__global__ void __launch_bounds__(256, 2) k_gemm(int xbuf, int obuf,
                                                 const float* __restrict__ root,
                                                 const float* __restrict__ basis,
                                                 const float* __restrict__ bias) {
    __shared__ unsigned As[128 * SMSTRIDE];   // [m][k] tf32
    __shared__ unsigned Bt[128 * SMSTRIDE];   // [n][k] tf32 (W transposed)

    const float* X = g_X[xbuf];
    int tid = threadIdx.x;
    int lane = tid & 31, wid = tid >> 5;
    int warp_m = wid & 3, warp_n = wid >> 2;
    int g = lane >> 2, tig = lane & 3;
    int m0 = blockIdx.x * 128;

    float d[2][8][4];
    #pragma unroll
    for (int mi = 0; mi < 2; mi++)
        #pragma unroll
        for (int ni = 0; ni < 8; ni++)
            #pragma unroll
            for (int q = 0; q < 4; q++) d[mi][ni][q] = 0.0f;

    #pragma unroll 1
    for (int c = 0; c < 20; c++) {
        int k0 = c * 32;
        // ---- A chunk: 128 rows x 32 k ----
        if (c < 4) {
            // from X (fp32)
            #pragma unroll
            for (int t = 0; t < 4; t++) {
                int idx = tid + t * 256;
                int row = idx >> 3, c4 = idx & 7;
                float4 v = make_float4(0.f, 0.f, 0.f, 0.f);
                if (m0 + row < N_ENT)
                    v = *(const float4*)(X + (size_t)(m0 + row) * DIM + k0 + c4 * 4);
                unsigned* p = As + row * SMSTRIDE + c4 * 4;
                p[0] = f2tf32(v.x); p[1] = f2tf32(v.y);
                p[2] = f2tf32(v.z); p[3] = f2tf32(v.w);
            }
        } else {
            // from Z (bf16): 32 bf16 per row = 4 uint4
            int zc0 = k0 - DIM;
            #pragma unroll
            for (int t = 0; t < 2; t++) {
                int idx = tid + t * 256;
                int row = idx >> 2, q = idx & 3;
                uint4 v = make_uint4(0u, 0u, 0u, 0u);
                if (m0 + row < N_ENT)
                    v = *(const uint4*)(g_Z + (size_t)(m0 + row) * ZCOLS + zc0 + q * 8);
                unsigned* p = As + row * SMSTRIDE + q * 8;
                const __nv_bfloat162* h = (const __nv_bfloat162*)&v;
                #pragma unroll
                for (int j = 0; j < 4; j++) {
                    float2 f = __bfloat1622float2(h[j]);
                    p[j * 2]     = f2tf32(f.x);
                    p[j * 2 + 1] = f2tf32(f.y);
                }
            }
        }
        // ---- B chunk: 32 k-rows x 128 n, direct from root/basis ----
        {
            const float* Bsrc = (c < 4) ? (root + (size_t)k0 * DIM)
                                        : (basis + (size_t)(k0 - DIM) * DIM);
            #pragma unroll
            for (int t = 0; t < 4; t++) {
                int idx = tid + t * 256;
                int kr = idx & 31, c4 = idx >> 5;
                float4 v = __ldg((const float4*)(Bsrc + (size_t)kr * DIM + c4 * 4));
                Bt[(c4 * 4 + 0) * SMSTRIDE + kr] = f2tf32(v.x);
                Bt[(c4 * 4 + 1) * SMSTRIDE + kr] = f2tf32(v.y);
                Bt[(c4 * 4 + 2) * SMSTRIDE + kr] = f2tf32(v.z);
                Bt[(c4 * 4 + 3) * SMSTRIDE + kr] = f2tf32(v.w);
            }
        }
        __syncthreads();

        #pragma unroll
        for (int kk = 0; kk < 4; kk++) {
            unsigned a[2][4], b[8][2];
            #pragma unroll
            for (int mi = 0; mi < 2; mi++) {
                int br = warp_m * 32 + mi * 16;
                a[mi][0] = As[(br + g) * SMSTRIDE + kk * 8 + tig];
                a[mi][1] = As[(br + g + 8) * SMSTRIDE + kk * 8 + tig];
                a[mi][2] = As[(br + g) * SMSTRIDE + kk * 8 + tig + 4];
                a[mi][3] = As[(br + g + 8) * SMSTRIDE + kk * 8 + tig + 4];
            }
            #pragma unroll
            for (int ni = 0; ni < 8; ni++) {
                int bn = warp_n * 64 + ni * 8;
                b[ni][0] = Bt[(bn + g) * SMSTRIDE + kk * 8 + tig];
                b[ni][1] = Bt[(bn + g) * SMSTRIDE + kk * 8 + tig + 4];
            }
            #pragma unroll
            for (int mi = 0; mi < 2; mi++)
                #pragma unroll
                for (int ni = 0; ni < 8; ni++) {
                    asm volatile(
                        "mma.sync.aligned.m16n8k8.row.col.f32.tf32.tf32.f32 "
                        "{%0,%1,%2,%3}, {%4,%5,%6,%7}, {%8,%9}, {%0,%1,%2,%3};"
                        : "+f"(d[mi][ni][0]), "+f"(d[mi][ni][1]),
                          "+f"(d[mi][ni][2]), "+f"(d[mi][ni][3])
                        : "r"(a[mi][0]), "r"(a[mi][1]), "r"(a[mi][2]), "r"(a[mi][3]),
                          "r"(b[ni][0]), "r"(b[ni][1]));
                }
        }
        __syncthreads();
    }

    // epilogue: + bias, relu, store fp32 to X[obuf]
    float* Xo = g_X[obuf];
    #pragma unroll
    for (int mi = 0; mi < 2; mi++) {
        int r0 = m0 + warp_m * 32 + mi * 16 + g;
        #pragma unroll
        for (int ni = 0; ni < 8; ni++) {
            int col = warp_n * 64 + ni * 8 + tig * 2;
            float b0 = __ldg(bias + col), b1 = __ldg(bias + col + 1);
            if (r0 < N_ENT) {
                float2 o = make_float2(fmaxf(d[mi][ni][0] + b0, 0.f),
                                       fmaxf(d[mi][ni][1] + b1, 0.f));
                *(float2*)(Xo + (size_t)r0 * DIM + col) = o;
            }
            if (r0 + 8 < N_ENT) {
                float2 o = make_float2(fmaxf(d[mi][ni][2] + b0, 0.f),
                                       fmaxf(d[mi][ni][3] + b1, 0.f));
                *(float2*)(Xo + (size_t)(r0 + 8) * DIM + col) = o;
            }
        }
    }
}

// ---------------- relation path (tiny) ----------------
__global__ void k_relT(const float* __restrict__ DAD, const float* __restrict__ rctx) {
    int idx = blockIdx.x * blockDim.x + threadIdx.x;
    if (idx >= NREL * DIM) return;
    int r = idx >> 7, o = idx & 127;
    float s = 0.f;
    for (int k = 0; k < NREL; k++)
        s += DAD[r * NREL + k] * rctx[k * DIM + o];
    g_T[idx] = s;
}

__global__ void k_relR(const float* __restrict__ W) {
    int idx = blockIdx.x * blockDim.x + threadIdx.x;
    if (idx >= NREL * DIM) return;
    int r = idx >> 7, o = idx & 127;
    float s = 0.f;
    for (int k = 0; k < DIM; k++)
        s += g_T[r * DIM + k] * W[k * DIM + o];
    g_R[idx] = fmaxf(s, 0.f);
}

// ---------------- final gated gather ----------------
__global__ void k_out(const int* __restrict__ samples,
                      const float* __restrict__ ent_emb,
                      const float* __restrict__ rel_emb,
                      const float* __restrict__ gate_e,
                      const float* __restrict__ gate_r,
                      int x2buf, float* __restrict__ out) {
    int idx = blockIdx.x * blockDim.x + threadIdx.x;
    if (idx >= S_NUM * DIM) return;
    int s = idx >> 7, d = idx & 127;
    int h = samples[s * 3 + 0];
    int r = samples[s * 3 + 1];
    int t = samples[s * 3 + 2];
    float ge = 1.0f / (1.0f + expf(-gate_e[d]));
    float gr = 1.0f / (1.0f + expf(-gate_r[d]));
    const float* X2 = g_X[x2buf];
    out[idx] = ge * ent_emb[(size_t)h * DIM + d] + (1.0f - ge) * X2[(size_t)h * DIM + d];
    out[S_NUM * DIM + idx] = gr * rel_emb[(size_t)r * DIM + d] + (1.0f - gr) * g_R[(size_t)r * DIM + d];
    out[2 * S_NUM * DIM + idx] = ge * ent_emb[(size_t)t * DIM + d] + (1.0f - ge) * X2[(size_t)t * DIM + d];
}

// ---------------- launch ----------------
extern "C" void kernel_launch(void* const* d_in, const int* in_sizes, int n_in,
                              void* d_out, int out_size) {
    const int*   entity    = (const int*)d_in[0];
    const int*   edge_index= (const int*)d_in[1];
    const int*   edge_type = (const int*)d_in[2];
    const float* edge_norm = (const float*)d_in[3];
    const int*   samples   = (const int*)d_in[4];
    const float* DAD       = (const float*)d_in[5];
    const float* ent_emb   = (const float*)d_in[6];
    const float* rel_emb   = (const float*)d_in[7];
    const float* ectx      = (const float*)d_in[8];
    const float* rctx      = (const float*)d_in[9];
    const float* gcnW      = (const float*)d_in[10];
    const float* gate_e    = (const float*)d_in[11];
    const float* gate_r    = (const float*)d_in[12];
    const float* basis1    = (const float*)d_in[13];
    const float* att1      = (const float*)d_in[14];
    const float* root1     = (const float*)d_in[15];
    const float* bias1     = (const float*)d_in[16];
    const float* basis2    = (const float*)d_in[17];
    const float* att2      = (const float*)d_in[18];
    const float* root2     = (const float*)d_in[19];
    const float* bias2     = (const float*)d_in[20];
    float* out = (float*)d_out;

    const int THR = 256;
    int gemm_grid = (N_ENT + 127) / 128;

    // ---- CSR build (shared by both layers) ----
    k_zero_cnt<<<(N_ENT + THR - 1) / THR, THR>>>();
    k_count<<<(E_NUM + THR - 1) / THR, THR>>>(edge_index);
    k_bsum<<<SCAN_NBLK, SCAN_BLK>>>();
    k_bscan<<<1, SCAN_NBLK>>>();
    k_expand<<<(N_ENT + THR - 1) / THR, THR>>>();
    k_scatter<<<(E_NUM + THR - 1) / THR, THR>>>(edge_index, edge_type, edge_norm);

    // initial features
    k_gather<<<(N_ENT * (DIM / 4) + THR - 1) / THR, THR>>>(entity, ectx);

    // ---- layer 1 ----
    k_aggZ<<<(N_ENT + 7) / 8, THR>>>(0, att1);
    k_gemm<<<gemm_grid, THR>>>(0, 1, root1, basis1, bias1);

    // ---- layer 2 ----
    k_aggZ<<<(N_ENT + 7) / 8, THR>>>(1, att2);
    k_gemm<<<gemm_grid, THR>>>(1, 0, root2, basis2, bias2);

    // ---- relation path ----
    k_relT<<<(NREL * DIM + THR - 1) / THR, THR>>>(DAD, rctx);
    k_relR<<<(NREL * DIM + THR - 1) / THR, THR>>>(gcnW);

    // ---- output ----
    k_out<<<(S_NUM * DIM + THR - 1) / THR, THR>>>(samples, ent_emb, rel_emb,
                                                  gate_e, gate_r, 0, out);
}